// round 3
// baseline (speedup 1.0000x reference)
#include <cuda_runtime.h>

// LightweightConv: depthwise temporal conv with per-head softmax weights.
// B=16, T=4000, C=512, H=8, K=31, PAD=15.
// out[b,t,c] = sum_k softmax(w)[c%8][k] * x[b, t-15+k, c] + bias[c%8]
//
// R3: weights in SMEM (frees ~60 regs for deeper x prefetch under
// launch_bounds(256,2)); streaming stores to keep halo lines in L2.

#define B_ 16
#define T_ 4000
#define C_ 512
#define H_ 8
#define K_ 31
#define PAD_ 15
#define TT 16   // t-outputs per thread; 4000 / 16 = 250 blocks in t

// Packed (per channel-pair) softmaxed weights and bias.
// Pair type p in [0,4): channels (2p, 2p+1) mod 8 -> heads (2p, 2p+1).
__device__ unsigned long long g_wpair[4][K_];
__device__ unsigned long long g_bpair[4];

__global__ void prep_kernel(const float* __restrict__ w,
                            const float* __restrict__ bias) {
    __shared__ float ws[H_][K_];
    int tid = threadIdx.x;
    if (tid < H_) {
        float m = -3.402823466e38f;
        #pragma unroll
        for (int k = 0; k < K_; k++) m = fmaxf(m, w[tid * K_ + k]);
        float e[K_];
        float s = 0.0f;
        #pragma unroll
        for (int k = 0; k < K_; k++) {
            e[k] = expf(w[tid * K_ + k] - m);
            s += e[k];
        }
        float inv = 1.0f / s;
        #pragma unroll
        for (int k = 0; k < K_; k++) ws[tid][k] = e[k] * inv;
    }
    __syncthreads();
    if (tid < 4 * K_) {
        int p = tid / K_;
        int k = tid % K_;
        float2 v = make_float2(ws[2 * p][k], ws[2 * p + 1][k]);
        g_wpair[p][k] = *reinterpret_cast<unsigned long long*>(&v);
    }
    if (tid < 4) {
        float2 v = make_float2(bias[2 * tid], bias[2 * tid + 1]);
        g_bpair[tid] = *reinterpret_cast<unsigned long long*>(&v);
    }
}

// Packed fp32x2 FMA (sm_100+): d = a*b + c elementwise on two packed floats.
__device__ __forceinline__ unsigned long long ffma2(unsigned long long a,
                                                    unsigned long long b,
                                                    unsigned long long c) {
    unsigned long long d;
    asm("fma.rn.f32x2 %0, %1, %2, %3;" : "=l"(d) : "l"(a), "l"(b), "l"(c));
    return d;
}

// Streaming 8B store (evict-first: output is never re-read; protect L2 halo).
__device__ __forceinline__ void stwt8(float* a, unsigned long long v) {
    asm volatile("st.global.cs.b64 [%0], %1;" :: "l"(a), "l"(v));
}

__global__ void __launch_bounds__(256, 2)
conv_kernel(const float* __restrict__ x, float* __restrict__ out) {
    // Per-pair packed weights in SMEM: 4 tables of 31 + bias.
    __shared__ unsigned long long s_w[4][K_];
    __shared__ unsigned long long s_b[4];

    const int tid = threadIdx.x;          // 0..255
    if (tid < 4 * K_) {
        int p = tid / K_;
        int k = tid % K_;
        s_w[p][k] = g_wpair[p][k];
    }
    if (tid < 4) s_b[tid] = g_bpair[tid];
    __syncthreads();

    const int c0 = tid << 1;              // channels c0, c0+1 (contiguous)
    const int p = tid & 3;                // pair type: heads (2p, 2p+1)
    const int b = blockIdx.y;
    const int t0 = blockIdx.x * TT;

    const unsigned long long bb = s_b[p];
    const unsigned long long* wp = s_w[p];

    unsigned long long acc[TT];
    #pragma unroll
    for (int j = 0; j < TT; j++) acc[j] = bb;

    const float* xp = x + ((size_t)b * T_) * C_ + c0;

    if (t0 >= PAD_ && t0 + TT + PAD_ <= T_) {
        // Interior fast path: no boundary predicates.
        const float* xq = xp + (size_t)(t0 - PAD_) * C_;
        #pragma unroll
        for (int i = 0; i < TT + 2 * PAD_; i++) {
            const unsigned long long xv = __ldg(
                reinterpret_cast<const unsigned long long*>(xq + (size_t)i * C_));
            #pragma unroll
            for (int j = 0; j < TT; j++) {
                if (i - j >= 0 && i - j < K_)   // constant-folds after unroll
                    acc[j] = ffma2(wp[i - j], xv, acc[j]);
            }
        }
    } else {
        // Boundary path: zero-padded loads.
        #pragma unroll
        for (int i = 0; i < TT + 2 * PAD_; i++) {
            const int t = t0 - PAD_ + i;
            unsigned long long xv = 0ull;
            if (t >= 0 && t < T_)
                xv = __ldg(reinterpret_cast<const unsigned long long*>(
                        xp + (size_t)t * C_));
            #pragma unroll
            for (int j = 0; j < TT; j++) {
                if (i - j >= 0 && i - j < K_)
                    acc[j] = ffma2(wp[i - j], xv, acc[j]);
            }
        }
    }

    float* op = out + ((size_t)b * T_ + t0) * C_ + c0;
    #pragma unroll
    for (int j = 0; j < TT; j++)
        stwt8(op + (size_t)j * C_, acc[j]);
}

extern "C" void kernel_launch(void* const* d_in, const int* in_sizes, int n_in,
                              void* d_out, int out_size) {
    const float* x    = (const float*)d_in[0];  // (B, T, C)
    const float* w    = (const float*)d_in[1];  // (H, 1, K)
    const float* bias = (const float*)d_in[2];  // (H,)
    float* out = (float*)d_out;                 // (B, T, C)

    prep_kernel<<<1, 128>>>(w, bias);

    dim3 grid(T_ / TT, B_);
    conv_kernel<<<grid, 256>>>(x, out);
}

// round 4
// speedup vs baseline: 1.2119x; 1.2119x over previous
#include <cuda_runtime.h>

// LightweightConv: depthwise temporal conv with per-head softmax weights.
// B=16, T=4000, C=512, H=8, K=31, PAD=15.
// out[b,t,c] = sum_k softmax(w)[c%8][k] * x[b, t-15+k, c] + bias[c%8]
//
// R4: back to R1 structure (weights resident in registers). TT 16->20
// (halo factor 2.875 -> 2.5) + streaming stores to preserve L2 for halo.

#define B_ 16
#define T_ 4000
#define C_ 512
#define H_ 8
#define K_ 31
#define PAD_ 15
#define TT 20   // t-outputs per thread; 4000 / 20 = 200 blocks in t

// Packed (per channel-pair) softmaxed weights and bias.
// Pair type p in [0,4): channels (2p, 2p+1) mod 8 -> heads (2p, 2p+1).
__device__ unsigned long long g_wpair[4][K_];
__device__ unsigned long long g_bpair[4];

__global__ void prep_kernel(const float* __restrict__ w,
                            const float* __restrict__ bias) {
    __shared__ float ws[H_][K_];
    int tid = threadIdx.x;
    if (tid < H_) {
        float m = -3.402823466e38f;
        #pragma unroll
        for (int k = 0; k < K_; k++) m = fmaxf(m, w[tid * K_ + k]);
        float e[K_];
        float s = 0.0f;
        #pragma unroll
        for (int k = 0; k < K_; k++) {
            e[k] = expf(w[tid * K_ + k] - m);
            s += e[k];
        }
        float inv = 1.0f / s;
        #pragma unroll
        for (int k = 0; k < K_; k++) ws[tid][k] = e[k] * inv;
    }
    __syncthreads();
    if (tid < 4 * K_) {
        int p = tid / K_;
        int k = tid % K_;
        float2 v = make_float2(ws[2 * p][k], ws[2 * p + 1][k]);
        g_wpair[p][k] = *reinterpret_cast<unsigned long long*>(&v);
    }
    if (tid < 4) {
        float2 v = make_float2(bias[2 * tid], bias[2 * tid + 1]);
        g_bpair[tid] = *reinterpret_cast<unsigned long long*>(&v);
    }
}

// Packed fp32x2 FMA (sm_100+): d = a*b + c elementwise on two packed floats.
__device__ __forceinline__ unsigned long long ffma2(unsigned long long a,
                                                    unsigned long long b,
                                                    unsigned long long c) {
    unsigned long long d;
    asm("fma.rn.f32x2 %0, %1, %2, %3;" : "=l"(d) : "l"(a), "l"(b), "l"(c));
    return d;
}

// Streaming 8B store (evict-first: output is never re-read; protect L2 halo).
__device__ __forceinline__ void stcs8(float* a, unsigned long long v) {
    asm volatile("st.global.cs.b64 [%0], %1;" :: "l"(a), "l"(v));
}

__global__ void __launch_bounds__(256, 2)
conv_kernel(const float* __restrict__ x, float* __restrict__ out) {
    const int tid = threadIdx.x;          // 0..255
    const int c0 = tid << 1;              // channels c0, c0+1 (contiguous)
    const int p = tid & 3;                // pair type: heads (2p, 2p+1)
    const int b = blockIdx.y;
    const int t0 = blockIdx.x * TT;

    // Weights for this channel pair (packed), resident in registers.
    unsigned long long wk[K_];
    #pragma unroll
    for (int k = 0; k < K_; k++) wk[k] = g_wpair[p][k];

    const unsigned long long bb = g_bpair[p];

    unsigned long long acc[TT];
    #pragma unroll
    for (int j = 0; j < TT; j++) acc[j] = bb;

    const float* xp = x + ((size_t)b * T_) * C_ + c0;

    if (t0 >= PAD_ && t0 + TT + PAD_ <= T_) {
        // Interior fast path: no boundary predicates.
        const float* xq = xp + (size_t)(t0 - PAD_) * C_;
        #pragma unroll
        for (int i = 0; i < TT + 2 * PAD_; i++) {
            const unsigned long long xv =
                *reinterpret_cast<const unsigned long long*>(xq + (size_t)i * C_);
            #pragma unroll
            for (int j = 0; j < TT; j++) {
                if (i - j >= 0 && i - j < K_)   // constant-folds after unroll
                    acc[j] = ffma2(wk[i - j], xv, acc[j]);
            }
        }
    } else {
        // Boundary path: zero-padded loads.
        #pragma unroll
        for (int i = 0; i < TT + 2 * PAD_; i++) {
            const int t = t0 - PAD_ + i;
            unsigned long long xv = 0ull;
            if (t >= 0 && t < T_)
                xv = *reinterpret_cast<const unsigned long long*>(xp + (size_t)t * C_);
            #pragma unroll
            for (int j = 0; j < TT; j++) {
                if (i - j >= 0 && i - j < K_)
                    acc[j] = ffma2(wk[i - j], xv, acc[j]);
            }
        }
    }

    float* op = out + ((size_t)b * T_ + t0) * C_ + c0;
    #pragma unroll
    for (int j = 0; j < TT; j++)
        stcs8(op + (size_t)j * C_, acc[j]);
}

extern "C" void kernel_launch(void* const* d_in, const int* in_sizes, int n_in,
                              void* d_out, int out_size) {
    const float* x    = (const float*)d_in[0];  // (B, T, C)
    const float* w    = (const float*)d_in[1];  // (H, 1, K)
    const float* bias = (const float*)d_in[2];  // (H,)
    float* out = (float*)d_out;                 // (B, T, C)

    prep_kernel<<<1, 128>>>(w, bias);

    dim3 grid(T_ / TT, B_);
    conv_kernel<<<grid, 256>>>(x, out);
}